// round 8
// baseline (speedup 1.0000x reference)
#include <cuda_runtime.h>
#include <cstdint>

#define BB 32
#define CC 128
#define HH 56
#define WW 56
#define SIZE (CC*HH*WW)          // 401408
#define HW   (HH*WW)             // 3136
#define EPSV 1e-5f
#define SLOPE 0.1f
#define SK 136                    // A smem row stride (floats), ≡ 8 mod 32
#define SB 72                     // B smem row stride (floats), ≡ 8 mod 32
#define SST (32*SK + 32*SB)       // per-stage floats: A(32*SK) + B(32*SB)

// scratch (allocation-free rule: __device__ globals)
__device__ float g_z[BB*SIZE];        // 51.4 MB: z = leakyrelu(bn1(combine))
__device__ float g_wt[9*CC*CC];       // [tap][ic][oc], tf32-rounded weights
__device__ float g_s2[CC];            // fused epilogue scale
__device__ float g_sh2[CC];           // fused epilogue shift (incl. conv bias)

__device__ __forceinline__ uint32_t f2tf32(float v) {
    uint32_t r; asm("cvt.rna.tf32.f32 %0, %1;" : "=r"(r) : "f"(v)); return r;
}
__device__ __forceinline__ uint32_t smem_u32(const void* p) {
    uint32_t a;
    asm("{ .reg .u64 t; cvta.to.shared.u64 t, %1; cvt.u32.u64 %0, t; }"
        : "=r"(a) : "l"(p));
    return a;
}
__device__ __forceinline__ void mma_tf32(float* d, const uint32_t* a,
                                         const uint32_t* b) {
    asm volatile(
        "mma.sync.aligned.m16n8k8.row.col.f32.tf32.tf32.f32 "
        "{%0,%1,%2,%3}, {%4,%5,%6,%7}, {%8,%9}, {%0,%1,%2,%3};"
        : "+f"(d[0]), "+f"(d[1]), "+f"(d[2]), "+f"(d[3])
        : "r"(a[0]), "r"(a[1]), "r"(a[2]), "r"(a[3]),
          "r"(b[0]), "r"(b[1]));
}

// ---------------------------------------------------------------------------
// Kernel 1: elementwise combine + BN1d + LeakyReLU
// ---------------------------------------------------------------------------
__global__ void scrm_fuse1(const float* __restrict__ ax,
                           const float* __restrict__ mx,
                           const float* __restrict__ cfc,
                           const float* __restrict__ gamma,
                           const float* __restrict__ beta,
                           const float* __restrict__ mean,
                           const float* __restrict__ var) {
    int i = blockIdx.x * blockDim.x + threadIdx.x;
    if (i >= SIZE) return;
    float w0 = cfc[2 * i];
    float w1 = cfc[2 * i + 1];
    float s  = gamma[i] * rsqrtf(var[i] + EPSV);
    float sh = beta[i] - mean[i] * s;
    float ws0 = w0 * s;
    float ws1 = w1 * s;
#pragma unroll 4
    for (int b = 0; b < BB; b++) {
        int idx = b * SIZE + i;
        float z = fmaf(ws0, ax[idx], fmaf(ws1, mx[idx], sh));
        g_z[idx] = (z > 0.f) ? z : SLOPE * z;
    }
}

// ---------------------------------------------------------------------------
// Kernel 1b: weight transpose [oc][ic][3][3] -> [tap][ic][oc], tf32-rounded
// ---------------------------------------------------------------------------
__global__ void scrm_wtrans(const float* __restrict__ gw) {
    int i = blockIdx.x * 256 + threadIdx.x;      // over 9*128*128
    if (i >= 9 * CC * CC) return;
    int oc = i & 127;
    int ic = (i >> 7) & 127;
    int t  = i >> 14;
    float v = gw[oc * 1152 + ic * 9 + t];
    g_wt[i] = __uint_as_float(f2tf32(v));        // [t][ic][oc]
}

// ---------------------------------------------------------------------------
// Kernel 1c: fold conv bias + BN2d into per-oc scale/shift
// ---------------------------------------------------------------------------
__global__ void scrm_epiparams(const float* __restrict__ cb,
                               const float* __restrict__ g2,
                               const float* __restrict__ b2,
                               const float* __restrict__ m2,
                               const float* __restrict__ v2) {
    int oc = threadIdx.x;
    float s = g2[oc] * rsqrtf(v2[oc] + EPSV);
    g_s2[oc]  = s;
    g_sh2[oc] = fmaf(cb[oc] - m2[oc], s, b2[oc]);
}

// ---------------------------------------------------------------------------
// Kernel 2: tf32 mma.sync implicit-GEMM conv, cp.async double-buffered.
// CTA: 256 thr (8 warps = 4 M x 2 N), block tile 128 px x 64 oc, K-chunk 32.
// Warp tile 32x32 -> acc 32 regs -> 3 CTAs/SM (24 warps) for tensor-pipe fill.
// Grid: (784 px-tiles, 2 oc-halves). 36 stages (9 taps x 4 ic-chunks).
// ---------------------------------------------------------------------------
__global__ void __launch_bounds__(256, 3)
scrm_conv_mma(float* __restrict__ out) {
    extern __shared__ float sm[];   // 2 stages x (As[32*SK] + Bs[32*SB])

    const int tid  = threadIdx.x;
    const int wid  = tid >> 5;
    const int lane = tid & 31;
    const int warp_m = wid & 3;     // 0..3  (4 M-warps x 32 px)
    const int warp_n = wid >> 2;    // 0..1  (2 N-warps x 32 oc)
    const int g   = lane >> 2;      // groupID 0..7
    const int tig = lane & 3;       // 0..3
    const int oc0 = blockIdx.y * 64;

    const int px   = tid & 127;     // gather: this thread's pixel column
    const int krow = tid >> 7;      // 0 or 1 (k rows krow, krow+2, ...)
    const int gp   = blockIdx.x * 128 + px;
    const int bb   = gp / HW;
    const int pp   = gp % HW;
    const int yy   = pp / WW, xx = pp % WW;
    const float* zb = g_z + (size_t)bb * SIZE;

    float acc[2][4][4];
#pragma unroll
    for (int mi = 0; mi < 2; mi++)
#pragma unroll
        for (int ni = 0; ni < 4; ni++)
#pragma unroll
            for (int j = 0; j < 4; j++) acc[mi][ni][j] = 0.f;

    // ---- stage prefetch: cp.async A-gather + B vector copy, one commit ----
    auto prefetch = [&](int s) {
        float* As = sm + (s & 1) * SST;
        float* Bs = As + 32 * SK;
        const int t = s >> 2, c = s & 3;
        const int t3 = t / 3;
        const int dy = t3 - 1, dx = (t - 3 * t3) - 1;
        const int iy = yy + dy, ix = xx + dx;
        const bool valid = ((unsigned)iy < (unsigned)HH) &
                           ((unsigned)ix < (unsigned)WW);
        const uint32_t asz = valid ? 4u : 0u;
        const float* ap = valid
            ? (zb + (size_t)(c * 32 + krow) * HW + iy * WW + ix)
            : zb;                                    // clamped, never read
        uint32_t adst = smem_u32(As + krow * SK + px);
#pragma unroll
        for (int i = 0; i < 16; i++) {
            asm volatile("cp.async.ca.shared.global [%0], [%1], 4, %2;"
                :: "r"(adst + (uint32_t)(i * 2 * SK * 4)),
                   "l"(ap + (size_t)i * 2 * HW), "r"(asz));
        }
        // B: [32 k][64 oc] = 512 float4 slots, 2 per thread
        const float* wb = g_wt + ((size_t)t * CC + c * 32) * CC + oc0;
#pragma unroll
        for (int q = 0; q < 2; q++) {
            int idx = tid + 256 * q;        // 0..511
            int r = idx >> 4, j = idx & 15;
            asm volatile("cp.async.ca.shared.global [%0], [%1], 16;"
                :: "r"(smem_u32(Bs + r * SB + j * 4)),
                   "l"(wb + r * CC + j * 4));
        }
        asm volatile("cp.async.commit_group;" ::: "memory");
    };

    prefetch(0);
    for (int s = 0; s < 36; ++s) {
        if (s + 1 < 36) {
            prefetch(s + 1);
            asm volatile("cp.async.wait_group 1;" ::: "memory");
        } else {
            asm volatile("cp.async.wait_group 0;" ::: "memory");
        }
        __syncthreads();

        const float* As = sm + (s & 1) * SST;
        const float* Bs = As + 32 * SK;
#pragma unroll
        for (int ks = 0; ks < 4; ks++) {
            const int k0 = ks * 8;
            const float* A0 = As + (k0 + tig) * SK;
            const float* A4 = As + (k0 + tig + 4) * SK;
            const float* B0 = Bs + (k0 + tig) * SB;
            const float* B4 = Bs + (k0 + tig + 4) * SB;
            uint32_t afr[2][4], bfr[4][2];
#pragma unroll
            for (int mi = 0; mi < 2; mi++) {
                int m = warp_m * 32 + mi * 16 + g;
                afr[mi][0] = __float_as_uint(A0[m]);
                afr[mi][1] = __float_as_uint(A0[m + 8]);
                afr[mi][2] = __float_as_uint(A4[m]);
                afr[mi][3] = __float_as_uint(A4[m + 8]);
            }
#pragma unroll
            for (int ni = 0; ni < 4; ni++) {
                int n = warp_n * 32 + ni * 8 + g;   // <= 63 < SB
                bfr[ni][0] = __float_as_uint(B0[n]);
                bfr[ni][1] = __float_as_uint(B4[n]);
            }
#pragma unroll
            for (int mi = 0; mi < 2; mi++)
#pragma unroll
                for (int ni = 0; ni < 4; ni++)
                    mma_tf32(acc[mi][ni], afr[mi], bfr[ni]);
        }
        __syncthreads();
    }

    // ---- epilogue: bias+BN2d+LeakyReLU, scatter to NCHW ----
#pragma unroll
    for (int mi = 0; mi < 2; mi++) {
#pragma unroll
        for (int half = 0; half < 2; half++) {
            int row = warp_m * 32 + mi * 16 + g + half * 8;   // <= 127
            int gpo = blockIdx.x * 128 + row;
            int bo  = gpo / HW;
            int po  = gpo % HW;
            float* obase = out + (size_t)bo * SIZE + po;
#pragma unroll
            for (int ni = 0; ni < 4; ni++) {
#pragma unroll
                for (int jj = 0; jj < 2; jj++) {
                    int oc = oc0 + warp_n * 32 + ni * 8 + 2 * tig + jj; // <=127
                    float v = fmaf(acc[mi][ni][half * 2 + jj],
                                   __ldg(&g_s2[oc]), __ldg(&g_sh2[oc]));
                    obase[(size_t)oc * HW] = (v > 0.f) ? v : SLOPE * v;
                }
            }
        }
    }
}

// ---------------------------------------------------------------------------
// launch
// ---------------------------------------------------------------------------
extern "C" void kernel_launch(void* const* d_in, const int* in_sizes, int n_in,
                              void* d_out, int out_size) {
    const float* ax   = (const float*)d_in[0];
    const float* mx   = (const float*)d_in[1];
    const float* cfc  = (const float*)d_in[2];
    const float* bng  = (const float*)d_in[3];
    const float* bnb  = (const float*)d_in[4];
    const float* bnm  = (const float*)d_in[5];
    const float* bnv  = (const float*)d_in[6];
    const float* cw   = (const float*)d_in[7];
    const float* cb   = (const float*)d_in[8];
    const float* g2   = (const float*)d_in[9];
    const float* b2   = (const float*)d_in[10];
    const float* m2   = (const float*)d_in[11];
    const float* v2   = (const float*)d_in[12];
    float* out = (float*)d_out;

    cudaFuncSetAttribute(scrm_conv_mma,
                         cudaFuncAttributeMaxDynamicSharedMemorySize,
                         2 * SST * sizeof(float));

    scrm_fuse1<<<(SIZE + 255) / 256, 256>>>(ax, mx, cfc, bng, bnb, bnm, bnv);
    scrm_wtrans<<<(9 * CC * CC + 255) / 256, 256>>>(cw);
    scrm_epiparams<<<1, CC>>>(cb, g2, b2, m2, v2);

    dim3 grid(BB * HW / 128, 2);     // 784 px-tiles x 2 oc-halves
    scrm_conv_mma<<<grid, 256, 2 * SST * sizeof(float)>>>(out);
}

// round 12
// speedup vs baseline: 1.7987x; 1.7987x over previous
#include <cuda_runtime.h>
#include <cuda_fp16.h>
#include <cstdint>

#define BB 32
#define CC 128
#define HH 56
#define WW 56
#define SIZE (CC*HH*WW)          // 401408
#define HW   (HH*WW)             // 3136
#define PH 58
#define PHW (PH*PH)              // 3364 padded plane
#define EPSV 1e-5f
#define SLOPE 0.1f
#define PITCH 272                 // smem row pitch bytes = 17*16 (odd 16B count)

// scratch (allocation-free rule: __device__ globals)
__device__ __half g_zh[BB*CC*PHW];    // 27.6 MB padded fp16 z
__device__ __half g_wth[9*CC*CC];     // [tap][ic][oc] fp16 weights
__device__ float  g_s2[CC];           // fused epilogue scale
__device__ float  g_sh2[CC];          // fused epilogue shift (incl. conv bias)

__device__ __forceinline__ uint32_t smem_u32(const void* p) {
    uint32_t a;
    asm("{ .reg .u64 t; cvta.to.shared.u64 t, %1; cvt.u32.u64 %0, t; }"
        : "=r"(a) : "l"(p));
    return a;
}
__device__ __forceinline__ void mma_f16(float* d, const uint32_t* a,
                                        const uint32_t* b) {
    asm volatile(
        "mma.sync.aligned.m16n8k16.row.col.f32.f16.f16.f32 "
        "{%0,%1,%2,%3}, {%4,%5,%6,%7}, {%8,%9}, {%0,%1,%2,%3};"
        : "+f"(d[0]), "+f"(d[1]), "+f"(d[2]), "+f"(d[3])
        : "r"(a[0]), "r"(a[1]), "r"(a[2]), "r"(a[3]),
          "r"(b[0]), "r"(b[1]));
}
#define LDSM_X4_T(r0, r1, r2, r3, addr) \
    asm volatile("ldmatrix.sync.aligned.m8n8.x4.trans.shared.b16 " \
                 "{%0,%1,%2,%3}, [%4];" \
                 : "=r"(r0), "=r"(r1), "=r"(r2), "=r"(r3) : "r"(addr))

// ---------------------------------------------------------------------------
// Kernel 1: combine + BN1d + LeakyReLU -> fp16 into padded [B][C][58][58]
// ---------------------------------------------------------------------------
__global__ void scrm_fuse1(const float* __restrict__ ax,
                           const float* __restrict__ mx,
                           const float* __restrict__ cfc,
                           const float* __restrict__ gamma,
                           const float* __restrict__ beta,
                           const float* __restrict__ mean,
                           const float* __restrict__ var) {
    int i = blockIdx.x * blockDim.x + threadIdx.x;
    if (i >= SIZE) return;
    float w0 = cfc[2 * i];
    float w1 = cfc[2 * i + 1];
    float s  = gamma[i] * rsqrtf(var[i] + EPSV);
    float sh = beta[i] - mean[i] * s;
    float ws0 = w0 * s;
    float ws1 = w1 * s;
    int c   = i / HW;
    int rem = i - c * HW;
    int y   = rem / WW;
    int x   = rem - y * WW;
    size_t zoff = (size_t)c * PHW + (y + 1) * PH + (x + 1);
#pragma unroll 4
    for (int b = 0; b < BB; b++) {
        int idx = b * SIZE + i;
        float z = fmaf(ws0, ax[idx], fmaf(ws1, mx[idx], sh));
        z = (z > 0.f) ? z : SLOPE * z;
        g_zh[(size_t)b * (CC * PHW) + zoff] = __float2half(z);
    }
}

// Kernel 1a: zero the padded borders (rows 0,57 and cols 0,57 per plane)
__global__ void scrm_borders() {
    int idx = blockIdx.x * blockDim.x + threadIdx.x;   // over BB*CC*58
    if (idx >= BB * CC * PH) return;
    int bc = idx / PH;
    int j  = idx - bc * PH;
    __half z = __float2half(0.f);
    size_t base = (size_t)bc * PHW;
    g_zh[base + j] = z;                    // row 0
    g_zh[base + 57 * PH + j] = z;          // row 57
    g_zh[base + j * PH] = z;               // col 0
    g_zh[base + j * PH + 57] = z;          // col 57
}

// Kernel 1b: weights [oc][ic][3][3] -> fp16 [tap][ic][oc]
__global__ void scrm_wtrans(const float* __restrict__ gw) {
    int i = blockIdx.x * 256 + threadIdx.x;      // over 9*128*128
    if (i >= 9 * CC * CC) return;
    int oc = i & 127;
    int ic = (i >> 7) & 127;
    int t  = i >> 14;
    g_wth[i] = __float2half(gw[oc * 1152 + ic * 9 + t]);
}

// Kernel 1c: fold conv bias + BN2d into per-oc scale/shift
__global__ void scrm_epiparams(const float* __restrict__ cb,
                               const float* __restrict__ g2,
                               const float* __restrict__ b2,
                               const float* __restrict__ m2,
                               const float* __restrict__ v2) {
    int oc = threadIdx.x;
    float s = g2[oc] * rsqrtf(v2[oc] + EPSV);
    g_s2[oc]  = s;
    g_sh2[oc] = fmaf(cb[oc] - m2[oc], s, b2[oc]);
}

// ---------------------------------------------------------------------------
// Kernel 2: fp16 mma.sync (m16n8k16) implicit-GEMM conv + fused epilogue.
// CTA: 256 thr (8 warps, 2 M x 4 N), block 128 px x 128 oc, K-chunk 32.
// Smem k-major, pitch 272B (odd 16B count): STS and ldmatrix.trans both
// conflict-free. A gather register-staged; B via cp.async; 2-stage buffer
// with TWO barriers per stage (top: data-ready; bottom: WAR protection for
// the next stage's cp.async/storeA writes — the missing bottom barrier was
// the R11 race).
// ---------------------------------------------------------------------------
__global__ void __launch_bounds__(256, 2)
scrm_conv_mma(float* __restrict__ out) {
    __shared__ __align__(16) unsigned char sA[2][32 * PITCH];
    __shared__ __align__(16) unsigned char sB[2][32 * PITCH];

    const int tid  = threadIdx.x;
    const int wid  = tid >> 5;
    const int lane = tid & 31;
    const int warp_m = wid >> 2;    // 0..1
    const int warp_n = wid & 3;     // 0..3
    const int g    = lane >> 2;     // 0..7
    const int tig  = lane & 3;      // 0..3
    const int grp  = lane >> 3;     // 0..3 (ldmatrix addr group)
    const int l8   = lane & 7;

    // gather role: thread owns px pair (2*pr, 2*pr+1), k rows krow+4i
    const int pr   = tid & 63;
    const int krow = tid >> 6;      // 0..3
    const int g2i  = blockIdx.x * 128 + 2 * pr;
    const int bb   = g2i / HW;
    const int pp   = g2i - bb * HW;
    const int yy   = pp / WW, xx = pp - (pp / WW) * WW;
    const __half* zbase = g_zh + (size_t)bb * (CC * PHW)
                        + (yy + 1) * PH + (xx + 1);

    // ldmatrix per-lane constant offsets
    const int kA_lane = (grp >> 1) * 8 + l8;           // A: k row add
    const int mA_lane = warp_m * 64 + (grp & 1) * 8;   // A: m col base
    const int kB_lane = (grp & 1) * 8 + l8;            // B: k row add
    const int nB_lane = warp_n * 32 + (grp >> 1) * 8;  // B: n col base

    float acc[4][4][4];
#pragma unroll
    for (int mi = 0; mi < 4; mi++)
#pragma unroll
        for (int ni = 0; ni < 4; ni++)
#pragma unroll
            for (int j = 0; j < 4; j++) acc[mi][ni][j] = 0.f;

    uint32_t areg[8];

    // --- B prefetch via cp.async (stage s -> buffer s&1) ---
    auto prefetchB = [&](int s) {
        unsigned char* Bs = sB[s & 1];
        const int t = s >> 2, c = s & 3;
        const __half* wb = g_wth + ((size_t)t * CC + c * 32) * CC;
#pragma unroll
        for (int q = 0; q < 2; q++) {
            int idx = tid + 256 * q;        // 0..511 = 32 rows x 16 x 16B
            int r = idx >> 4, j = idx & 15;
            asm volatile("cp.async.ca.shared.global [%0], [%1], 16;"
                :: "r"(smem_u32(Bs + r * PITCH + j * 16)),
                   "l"(wb + (size_t)r * CC + j * 8));
        }
        asm volatile("cp.async.commit_group;" ::: "memory");
    };

    // --- A gather into registers (LDG.U16 pairs, padded buffer: no bounds) ---
    auto gatherA = [&](int s) {
        const int t = s >> 2, c = s & 3;
        const int t3 = t / 3;
        const int dy = t3 - 1, dx = (t - 3 * t3) - 1;
        const __half* p = zbase + (size_t)(c * 32 + krow) * PHW + dy * PH + dx;
#pragma unroll
        for (int i = 0; i < 8; i++) {
            const __half* pi = p + (size_t)i * 4 * PHW;
            unsigned short h0 = *(const unsigned short*)pi;
            unsigned short h1 = *(const unsigned short*)(pi + 1);
            areg[i] = (uint32_t)h0 | ((uint32_t)h1 << 16);
        }
    };
    // --- A store regs -> smem (half2 STS, conflict-free) ---
    auto storeA = [&](int s) {
        uint32_t* As = (uint32_t*)sA[s & 1];
#pragma unroll
        for (int i = 0; i < 8; i++)
            As[(krow + 4 * i) * (PITCH / 4) + pr] = areg[i];
    };

    prefetchB(0);
    gatherA(0);
    storeA(0);

    for (int s = 0; s < 36; ++s) {
        // Safe: bottom barrier of stage s-1 guarantees everyone finished
        // reading sB[(s+1)&1] (last read in stage s-1's compute).
        if (s + 1 < 36) {
            prefetchB(s + 1);
            asm volatile("cp.async.wait_group 1;" ::: "memory");
        } else {
            asm volatile("cp.async.wait_group 0;" ::: "memory");
        }
        __syncthreads();                 // A(s) + B(s) visible to all warps

        if (s + 1 < 36) gatherA(s + 1);  // issue LDGs early (registers only)

        const uint32_t Abase = smem_u32(sA[s & 1]);
        const uint32_t Bbase = smem_u32(sB[s & 1]);
#pragma unroll
        for (int ks = 0; ks < 2; ks++) {
            const uint32_t Ak = Abase + (ks * 16 + kA_lane) * PITCH;
            const uint32_t Bk = Bbase + (ks * 16 + kB_lane) * PITCH;
            uint32_t afr[4][4], bt[2][4];
#pragma unroll
            for (int mi = 0; mi < 4; mi++)
                LDSM_X4_T(afr[mi][0], afr[mi][1], afr[mi][2], afr[mi][3],
                          Ak + (mA_lane + mi * 16) * 2);
#pragma unroll
            for (int nj = 0; nj < 2; nj++)
                LDSM_X4_T(bt[nj][0], bt[nj][1], bt[nj][2], bt[nj][3],
                          Bk + (nB_lane + nj * 16) * 2);
#pragma unroll
            for (int mi = 0; mi < 4; mi++) {
#pragma unroll
                for (int ni = 0; ni < 4; ni++)
                    mma_f16(acc[mi][ni], afr[mi], &bt[ni >> 1][2 * (ni & 1)]);
            }
        }
        if (s + 1 < 36) storeA(s + 1);   // other buffer; top sync protected
        __syncthreads();                 // WAR: stage s reads done before
                                         // next iteration's prefetchB writes
    }

    // ---- epilogue: bias+BN2d+LeakyReLU, scatter to NCHW ----
#pragma unroll
    for (int mi = 0; mi < 4; mi++) {
#pragma unroll
        for (int half = 0; half < 2; half++) {
            int row = warp_m * 64 + mi * 16 + g + half * 8;
            int gpo = blockIdx.x * 128 + row;
            int bo  = gpo / HW;
            int po  = gpo - bo * HW;
            float* obase = out + (size_t)bo * SIZE + po;
#pragma unroll
            for (int ni = 0; ni < 4; ni++) {
#pragma unroll
                for (int jj = 0; jj < 2; jj++) {
                    int oc = warp_n * 32 + ni * 8 + 2 * tig + jj;
                    float v = fmaf(acc[mi][ni][half * 2 + jj],
                                   __ldg(&g_s2[oc]), __ldg(&g_sh2[oc]));
                    obase[(size_t)oc * HW] = (v > 0.f) ? v : SLOPE * v;
                }
            }
        }
    }
}

// ---------------------------------------------------------------------------
// launch
// ---------------------------------------------------------------------------
extern "C" void kernel_launch(void* const* d_in, const int* in_sizes, int n_in,
                              void* d_out, int out_size) {
    const float* ax   = (const float*)d_in[0];
    const float* mx   = (const float*)d_in[1];
    const float* cfc  = (const float*)d_in[2];
    const float* bng  = (const float*)d_in[3];
    const float* bnb  = (const float*)d_in[4];
    const float* bnm  = (const float*)d_in[5];
    const float* bnv  = (const float*)d_in[6];
    const float* cw   = (const float*)d_in[7];
    const float* cb   = (const float*)d_in[8];
    const float* g2   = (const float*)d_in[9];
    const float* b2   = (const float*)d_in[10];
    const float* m2   = (const float*)d_in[11];
    const float* v2   = (const float*)d_in[12];
    float* out = (float*)d_out;

    scrm_borders<<<(BB * CC * PH + 255) / 256, 256>>>();
    scrm_fuse1<<<(SIZE + 255) / 256, 256>>>(ax, mx, cfc, bng, bnb, bnm, bnv);
    scrm_wtrans<<<(9 * CC * CC + 255) / 256, 256>>>(cw);
    scrm_epiparams<<<1, CC>>>(cb, g2, b2, m2, v2);

    scrm_conv_mma<<<BB * HW / 128, 256>>>(out);   // 784 CTAs
}

// round 13
// speedup vs baseline: 1.8377x; 1.0217x over previous
#include <cuda_runtime.h>
#include <cuda_fp16.h>
#include <cstdint>

#define BB 32
#define CC 128
#define HH 56
#define WW 56
#define SIZE (CC*HH*WW)          // 401408
#define HW   (HH*WW)             // 3136
#define PH 58
#define PHW (PH*PH)              // 3364 padded plane
#define EPSV 1e-5f
#define SLOPE 0.1f
#define APITCH 144                // conv smem row pitch bytes (9*16, odd 16B count)
#define STAGE_BYTES (2*128*APITCH)   // A + B tiles per stage = 36864
#define FP 66                     // fuse1 smem pitch (halves), 132B, /4 = 33 odd

// scratch (allocation-free rule: __device__ globals)
__device__ __align__(256) __half g_zh[(size_t)BB*PHW*CC]; // 27.6MB NHWC padded z
__device__ __align__(256) __half g_wth[9*CC*CC];          // [tap][oc][ic] fp16
__device__ __align__(256) float4 g_fold[SIZE];            // (ws0, ws1, sh, 0)
__device__ float  g_s2[CC];
__device__ float  g_sh2[CC];

__device__ __forceinline__ uint32_t smem_u32(const void* p) {
    uint32_t a;
    asm("{ .reg .u64 t; cvta.to.shared.u64 t, %1; cvt.u32.u64 %0, t; }"
        : "=r"(a) : "l"(p));
    return a;
}
__device__ __forceinline__ void mma_f16(float* d, const uint32_t* a,
                                        const uint32_t* b) {
    asm volatile(
        "mma.sync.aligned.m16n8k16.row.col.f32.f16.f16.f32 "
        "{%0,%1,%2,%3}, {%4,%5,%6,%7}, {%8,%9}, {%0,%1,%2,%3};"
        : "+f"(d[0]), "+f"(d[1]), "+f"(d[2]), "+f"(d[3])
        : "r"(a[0]), "r"(a[1]), "r"(a[2]), "r"(a[3]),
          "r"(b[0]), "r"(b[1]));
}
#define LDSM_X4(r0, r1, r2, r3, addr) \
    asm volatile("ldmatrix.sync.aligned.m8n8.x4.shared.b16 " \
                 "{%0,%1,%2,%3}, [%4];" \
                 : "=r"(r0), "=r"(r1), "=r"(r2), "=r"(r3) : "r"(addr))

// ---------------------------------------------------------------------------
// Setup (one launch): param fold + weight transpose + NHWC borders + epilogue
// params. All branches independent, indexed off one grid.
// ---------------------------------------------------------------------------
__global__ void scrm_setup(const float* __restrict__ cfc,
                           const float* __restrict__ gamma,
                           const float* __restrict__ beta,
                           const float* __restrict__ mean,
                           const float* __restrict__ var,
                           const float* __restrict__ gw,
                           const float* __restrict__ cb,
                           const float* __restrict__ g2,
                           const float* __restrict__ b2,
                           const float* __restrict__ m2,
                           const float* __restrict__ v2) {
    int idx = blockIdx.x * 256 + threadIdx.x;
    if (idx < SIZE) {                       // fold BN1 into (ws0, ws1, sh)
        float s = gamma[idx] * rsqrtf(var[idx] + EPSV);
        float4 f;
        f.x = cfc[2 * idx] * s;
        f.y = cfc[2 * idx + 1] * s;
        f.z = beta[idx] - mean[idx] * s;
        f.w = 0.f;
        g_fold[idx] = f;
    }
    if (idx < 9 * CC * CC) {                // weights -> [tap][oc][ic] fp16
        int ic = idx & 127;
        int oc = (idx >> 7) & 127;
        int t  = idx >> 14;
        g_wth[idx] = __float2half(gw[oc * 1152 + ic * 9 + t]);
    }
    if (idx < BB * 3648) {                  // zero NHWC borders, 16B per idx
        int b = idx / 3648;
        int r = idx - b * 3648;
        int off;                            // halves within plane
        if (r < 928)       off = (r >> 4) * CC + (r & 15) * 8;               // y=0
        else if (r < 1856) { int q = r - 928;  off = (57 * PH + (q >> 4)) * CC + (q & 15) * 8; }
        else if (r < 2752) { int q = r - 1856; off = ((1 + (q >> 4)) * PH) * CC + (q & 15) * 8; }
        else               { int q = r - 2752; off = ((1 + (q >> 4)) * PH + 57) * CC + (q & 15) * 8; }
        uint4 z4 = {0u, 0u, 0u, 0u};
        *(uint4*)(g_zh + (size_t)b * PHW * CC + off) = z4;
    }
    if (idx < CC) {                         // epilogue scale/shift
        float s = g2[idx] * rsqrtf(v2[idx] + EPSV);
        g_s2[idx]  = s;
        g_sh2[idx] = fmaf(cb[idx] - m2[idx], s, b2[idx]);
    }
}

// ---------------------------------------------------------------------------
// Kernel 1: combine + BN1d + LeakyReLU -> fp16 NHWC padded [B][58][58][128].
// Block = (y, c-half). Folded params live in REGISTERS (read once), loop b;
// smem transpose per b -> fully coalesced 128B NHWC writes.
// ---------------------------------------------------------------------------
__global__ void __launch_bounds__(256, 1)
scrm_fuse1(const float* __restrict__ ax, const float* __restrict__ mx) {
    __shared__ __half zs[WW * FP];          // [x][c] pitch 66 halves

    const int t    = threadIdx.x;
    const int y    = blockIdx.x;            // 0..55
    const int coff = blockIdx.y * 64;       // c half

    float4 fold[14];
    int    off[14];
    int    sts[14];
#pragma unroll
    for (int j = 0; j < 14; j++) {
        int elem = t + 256 * j;             // < 3584 = 64c x 56x
        int c = elem / 56;
        int x = elem - c * 56;
        off[j] = (coff + c) * HW + y * WW + x;
        sts[j] = x * FP + c;
        fold[j] = g_fold[off[j]];
    }

    for (int b = 0; b < BB; b++) {
        const float* axb = ax + (size_t)b * SIZE;
        const float* mxb = mx + (size_t)b * SIZE;
#pragma unroll
        for (int j = 0; j < 14; j++) {
            float a = __ldg(axb + off[j]);
            float m = __ldg(mxb + off[j]);
            float z = fmaf(fold[j].x, a, fmaf(fold[j].y, m, fold[j].z));
            z = (z > 0.f) ? z : SLOPE * z;
            zs[sts[j]] = __float2half(z);
        }
        __syncthreads();
        __half* orow = g_zh + ((size_t)b * PHW + (y + 1) * PH + 1) * CC + coff;
#pragma unroll
        for (int m2 = 0; m2 < 2; m2++) {
            int idx = t + 256 * m2;
            if (idx < 448) {                // 56 px x 8 segs(16B) of this half
                int px = idx >> 3, seg = idx & 7;
                const uint32_t* zp = (const uint32_t*)
                    ((const char*)zs + px * (FP * 2) + seg * 16);
                uint4 v;
                v.x = zp[0]; v.y = zp[1]; v.z = zp[2]; v.w = zp[3];
                *(uint4*)(orow + (size_t)px * CC + seg * 8) = v;
            }
        }
        __syncthreads();
    }
}

// ---------------------------------------------------------------------------
// Kernel 2: fp16 mma.sync implicit-GEMM conv, NHWC A via pure cp.async.
// CTA: 256 thr (8 warps, 2 M x 4 N), block 128 px x 128 oc, K-chunk 64.
// 18 stages (9 taps x 2 c-chunks). Smem tiles [row][k] k-contiguous,
// pitch 144B (odd 16B count): cp.async dst and non-trans ldmatrix both
// conflict-free. Two barriers per stage (data-ready + WAR).
// ---------------------------------------------------------------------------
__global__ void __launch_bounds__(256, 2)
scrm_conv_mma(float* __restrict__ out) {
    extern __shared__ unsigned char smem[];   // 2 stages x (A + B)

    const int tid  = threadIdx.x;
    const int wid  = tid >> 5;
    const int lane = tid & 31;
    const int warp_m = wid >> 2;    // 0..1
    const int warp_n = wid & 3;     // 0..3
    const int g    = lane >> 2;     // 0..7
    const int tig  = lane & 3;      // 0..3

    // per-thread A-copy roles: 4 pixels (t>>3 + 32q), seg = t&7
    const int seg8 = (tid & 7) * 8;           // halves within 64-c chunk? no: 16B seg
    const __half* aptr[4];
#pragma unroll
    for (int q = 0; q < 4; q++) {
        int px = (tid >> 3) + 32 * q;
        int gp = blockIdx.x * 128 + px;
        int b  = gp / HW;
        int p  = gp - b * HW;
        int yy = p / WW, xx = p - (p / WW) * WW;
        aptr[q] = g_zh + ((size_t)b * PHW + (yy + 1) * PH + (xx + 1)) * CC;
    }

    // ldmatrix lane-constant addressing
    const int rA   = warp_m * 64 + (lane & 15);   // + mi*16 rows
    const int rB   = warp_n * 32 + (lane & 15);   // + nj*16 rows
    const int csel = (lane >> 4) * 16;            // byte col select

    float acc[4][4][4];
#pragma unroll
    for (int mi = 0; mi < 4; mi++)
#pragma unroll
        for (int ni = 0; ni < 4; ni++)
#pragma unroll
            for (int j = 0; j < 4; j++) acc[mi][ni][j] = 0.f;

    auto prefetch = [&](int s) {
        unsigned char* As = smem + (s & 1) * STAGE_BYTES;
        unsigned char* Bs = As + 128 * APITCH;
        const int tap = s >> 1;
        const int c0  = (s & 1) * 64;             // halves
        const int t3  = tap / 3;
        const int doff = ((t3 - 1) * PH + (tap - 3 * t3 - 1)) * CC + c0;
        const uint32_t dA = smem_u32(As) + (tid >> 3) * APITCH + (tid & 7) * 16;
#pragma unroll
        for (int q = 0; q < 4; q++) {
            asm volatile("cp.async.ca.shared.global [%0], [%1], 16;"
                :: "r"(dA + (uint32_t)(32 * q * APITCH)),
                   "l"(aptr[q] + doff + (tid & 7) * 8));
        }
        const __half* wb = g_wth + (size_t)tap * (CC * CC) + c0;
        const uint32_t dB = smem_u32(Bs);
#pragma unroll
        for (int q = 0; q < 4; q++) {
            int idx = tid + 256 * q;              // 0..1023
            int oc = idx >> 3, sg = idx & 7;
            asm volatile("cp.async.ca.shared.global [%0], [%1], 16;"
                :: "r"(dB + oc * APITCH + sg * 16),
                   "l"(wb + (size_t)oc * CC + sg * 8));
        }
        asm volatile("cp.async.commit_group;" ::: "memory");
    };

    prefetch(0);
    for (int s = 0; s < 18; ++s) {
        if (s + 1 < 18) {
            prefetch(s + 1);
            asm volatile("cp.async.wait_group 1;" ::: "memory");
        } else {
            asm volatile("cp.async.wait_group 0;" ::: "memory");
        }
        __syncthreads();                          // stage s data ready

        const uint32_t Abase = smem_u32(smem + (s & 1) * STAGE_BYTES);
        const uint32_t Bbase = Abase + 128 * APITCH;
#pragma unroll
        for (int ks = 0; ks < 4; ks++) {
            const int cb = ks * 32 + csel;
            uint32_t afr[4][4], bt[2][4];
#pragma unroll
            for (int mi = 0; mi < 4; mi++)
                LDSM_X4(afr[mi][0], afr[mi][1], afr[mi][2], afr[mi][3],
                        Abase + (rA + mi * 16) * APITCH + cb);
#pragma unroll
            for (int nj = 0; nj < 2; nj++)
                LDSM_X4(bt[nj][0], bt[nj][1], bt[nj][2], bt[nj][3],
                        Bbase + (rB + nj * 16) * APITCH + cb);
#pragma unroll
            for (int mi = 0; mi < 4; mi++) {
#pragma unroll
                for (int ni = 0; ni < 4; ni++) {
                    uint32_t bfr[2] = { bt[ni >> 1][ni & 1],
                                        bt[ni >> 1][(ni & 1) + 2] };
                    mma_f16(acc[mi][ni], afr[mi], bfr);
                }
            }
        }
        __syncthreads();                          // WAR before next prefetch
    }

    // ---- epilogue: bias+BN2d+LeakyReLU, scatter to NCHW out ----
#pragma unroll
    for (int mi = 0; mi < 4; mi++) {
#pragma unroll
        for (int half = 0; half < 2; half++) {
            int row = warp_m * 64 + mi * 16 + g + half * 8;
            int gpo = blockIdx.x * 128 + row;
            int bo  = gpo / HW;
            int po  = gpo - bo * HW;
            float* obase = out + (size_t)bo * SIZE + po;
#pragma unroll
            for (int ni = 0; ni < 4; ni++) {
#pragma unroll
                for (int jj = 0; jj < 2; jj++) {
                    int oc = warp_n * 32 + ni * 8 + 2 * tig + jj;
                    float v = fmaf(acc[mi][ni][half * 2 + jj],
                                   __ldg(&g_s2[oc]), __ldg(&g_sh2[oc]));
                    obase[(size_t)oc * HW] = (v > 0.f) ? v : SLOPE * v;
                }
            }
        }
    }
}

// ---------------------------------------------------------------------------
// launch
// ---------------------------------------------------------------------------
extern "C" void kernel_launch(void* const* d_in, const int* in_sizes, int n_in,
                              void* d_out, int out_size) {
    const float* ax   = (const float*)d_in[0];
    const float* mx   = (const float*)d_in[1];
    const float* cfc  = (const float*)d_in[2];
    const float* bng  = (const float*)d_in[3];
    const float* bnb  = (const float*)d_in[4];
    const float* bnm  = (const float*)d_in[5];
    const float* bnv  = (const float*)d_in[6];
    const float* cw   = (const float*)d_in[7];
    const float* cb   = (const float*)d_in[8];
    const float* g2   = (const float*)d_in[9];
    const float* b2   = (const float*)d_in[10];
    const float* m2   = (const float*)d_in[11];
    const float* v2   = (const float*)d_in[12];
    float* out = (float*)d_out;

    cudaFuncSetAttribute(scrm_conv_mma,
                         cudaFuncAttributeMaxDynamicSharedMemorySize,
                         2 * STAGE_BYTES);

    scrm_setup<<<(SIZE + 255) / 256, 256>>>(cfc, bng, bnb, bnm, bnv,
                                            cw, cb, g2, b2, m2, v2);
    dim3 fgrid(HH, 2);
    scrm_fuse1<<<fgrid, 256>>>(ax, mx);
    scrm_conv_mma<<<BB * HW / 128, 256, 2 * STAGE_BYTES>>>(out);
}